// round 14
// baseline (speedup 1.0000x reference)
#include <cuda_runtime.h>
#include <cuda_fp16.h>
#include <cstdint>
#include <math.h>

#define T_   8192
#define H_   2048
#define NH_  16
#define NKV_ 4
#define D_   128
#define CH   64
#define NC   128          // T_/CH
#define QKVW 3072
#define GK   2048

// ---------------- scratch (static device memory) ------------------------------
__device__ __align__(256) float g_tmp16[(size_t)T_ * 16];
__device__ __align__(256) float g_eB[(size_t)T_ * 512];     // exp(B) per (t,kv,d)
__device__ __align__(256) float g_EB[(size_t)NC * NKV_ * D_];
__device__ __align__(256) __half g_P16[(size_t)NC * NKV_ * D_ * D_];
__device__ __align__(256) __half g_S16[(size_t)NC * NKV_ * D_ * D_];
// fp16 operands
__device__ __align__(256) __half g_hA16[(size_t)T_ * H_];
__device__ __align__(256) __half g_Wq16[(size_t)QKVW * GK];   // [N,K]
__device__ __align__(256) __half g_Wo16[(size_t)H_ * GK];     // [N,K]
__device__ __align__(256) __half g_oA16[(size_t)T_ * H_];
__device__ __align__(256) __half g_q16[(size_t)T_ * 2048];    // q*scale (gate-unscaled)
__device__ __align__(256) __half g_k16[(size_t)T_ * 512];     // k~ after gateB
__device__ __align__(256) __half g_v16[(size_t)T_ * 512];

// ======================= PTX helpers ==========================================
__device__ __forceinline__ uint32_t smem_u32(const void* p) {
    uint32_t a;
    asm("{ .reg .u64 t; cvta.to.shared.u64 t, %1; cvt.u32.u64 %0, t; }" : "=r"(a) : "l"(p));
    return a;
}
__device__ __forceinline__ void cpa16(uint32_t dst, const void* src) {
    asm volatile("cp.async.cg.shared.global [%0], [%1], 16;" :: "r"(dst), "l"(src));
}
__device__ __forceinline__ void ldsm4(uint32_t* r, uint32_t addr) {
    asm volatile("ldmatrix.sync.aligned.m8n8.x4.shared.b16 {%0,%1,%2,%3}, [%4];"
                 : "=r"(r[0]), "=r"(r[1]), "=r"(r[2]), "=r"(r[3]) : "r"(addr));
}
__device__ __forceinline__ void ldsm4t(uint32_t* r, uint32_t addr) {
    asm volatile("ldmatrix.sync.aligned.m8n8.x4.trans.shared.b16 {%0,%1,%2,%3}, [%4];"
                 : "=r"(r[0]), "=r"(r[1]), "=r"(r[2]), "=r"(r[3]) : "r"(addr));
}
__device__ __forceinline__ void mma16816(float* d, const uint32_t* a,
                                         uint32_t b0, uint32_t b1) {
    asm volatile("mma.sync.aligned.m16n8k16.row.col.f32.f16.f16.f32 "
                 "{%0,%1,%2,%3}, {%4,%5,%6,%7}, {%8,%9}, {%0,%1,%2,%3};"
                 : "+f"(d[0]), "+f"(d[1]), "+f"(d[2]), "+f"(d[3])
                 : "r"(a[0]), "r"(a[1]), "r"(a[2]), "r"(a[3]), "r"(b0), "r"(b1));
}

// ======================= fused prep: wtrans x2 + (split ∪ gk1) =================
// blocks [0,6144): Wqkv [2048,3072] -> [3072,2048] fp16
// blocks [6144,10240): Wo [2048,2048] -> [2048,2048] fp16
// blocks [10240,18432): row t: hidden fp32 -> fp16 AND gk1 accumulation
__global__ void __launch_bounds__(256) prep_kernel(
    const float* __restrict__ hidden, const float* __restrict__ Wqkv,
    const float* __restrict__ Wo, const float* __restrict__ w0,
    __half* __restrict__ hA16, __half* __restrict__ Wq16, __half* __restrict__ Wo16) {
    __shared__ float sm[8 * 17];
    __shared__ float smt[32][33];
    int b = blockIdx.x, tid = threadIdx.x;
    if (b < 10240) {
        const float* W;
        __half* out;
        int bx, by, N;
        if (b < 6144) { N = QKVW; bx = b % 96; by = b / 96; W = Wqkv; out = Wq16; }
        else          { int v = b - 6144; N = H_; bx = v % 64; by = v / 64; W = Wo; out = Wo16; }
        int lx = tid & 31, ly = tid >> 5;
        for (int r = ly; r < 32; r += 8)
            smt[r][lx] = W[(size_t)(by * 32 + r) * N + bx * 32 + lx];
        __syncthreads();
        for (int r = ly; r < 32; r += 8)
            out[(size_t)(bx * 32 + r) * GK + by * 32 + lx] = __float2half_rn(smt[lx][r]);
        return;
    }
    // row t: fp16 conversion + gk1 in one pass over hidden[t]
    int t = b - 10240;
    int h0 = tid * 8;
    const float* hrow = hidden + (size_t)t * H_;
    float4 a0 = *(const float4*)(hrow + h0);
    float4 a1 = *(const float4*)(hrow + h0 + 4);
    __half2* dst = (__half2*)(hA16 + (size_t)t * H_ + h0);
    dst[0] = __floats2half2_rn(a0.x, a0.y);
    dst[1] = __floats2half2_rn(a0.z, a0.w);
    dst[2] = __floats2half2_rn(a1.x, a1.y);
    dst[3] = __floats2half2_rn(a1.z, a1.w);

    float acc[16];
#pragma unroll
    for (int r = 0; r < 16; r++) acc[r] = 0.f;
    float xs[8] = {a0.x, a0.y, a0.z, a0.w, a1.x, a1.y, a1.z, a1.w};
#pragma unroll
    for (int j = 0; j < 8; j++) {
        const float4* w = (const float4*)(w0 + (size_t)(h0 + j) * 16);
#pragma unroll
        for (int q = 0; q < 4; q++) {
            float4 w4 = w[q];
            acc[q * 4 + 0] += xs[j] * w4.x;
            acc[q * 4 + 1] += xs[j] * w4.y;
            acc[q * 4 + 2] += xs[j] * w4.z;
            acc[q * 4 + 3] += xs[j] * w4.w;
        }
    }
    // warp butterfly reduce all 16 accumulators
#pragma unroll
    for (int r = 0; r < 16; r++) {
#pragma unroll
        for (int m = 16; m >= 1; m >>= 1)
            acc[r] += __shfl_xor_sync(0xffffffffu, acc[r], m);
    }
    int wid = tid >> 5, lane = tid & 31;
    if (lane < 16) sm[wid * 17 + lane] = acc[lane];
    __syncthreads();
    if (tid < 16) {
        float s = 0.f;
#pragma unroll
        for (int w = 0; w < 8; w++) s += sm[w * 17 + tid];
        g_tmp16[(size_t)t * 16 + tid] = s;
    }
}

// ======================= HMMA GEMM: 128 thr, 4 warps 64x64, 2 CTAs/SM =========
#define ROWB   80
#define TILEB  (128 * ROWB)          // 10240
#define STAGEB (2 * TILEB)           // 20480 (A + B)
#define GSMEM  (4 * STAGEB)          // 81920 -> 2 CTAs/SM

__global__ void __launch_bounds__(128) gemm_mma(
    const __half* __restrict__ A16, const __half* __restrict__ B16,
    const float* __restrict__ bias, float* __restrict__ C, int N, int mode) {
    extern __shared__ char smraw[];
    uint32_t sbase = smem_u32(smraw);
    int tid = threadIdx.x, wid = tid >> 5, lane = tid & 31;
    int tm = blockIdx.y * 128, tn = blockIdx.x * 128;
    int wm = wid & 1, wn = wid >> 1;      // warp tile 64(M) x 64(N)

    float acc[4][8][4];
#pragma unroll
    for (int i = 0; i < 4; i++)
#pragma unroll
        for (int j = 0; j < 8; j++)
#pragma unroll
            for (int r = 0; r < 4; r++) acc[i][j][r] = 0.f;

    auto issue_load = [&](int k0i, int stage) {
        int k0 = k0i * 32;
        uint32_t sb = sbase + stage * STAGEB;
#pragma unroll
        for (int it = 0; it < 8; it++) {
            int u = tid + it * 128;
            const __half* src;
            uint32_t dst;
            if (u < 512) {
                int row = u >> 2, chunk = u & 3;
                src = A16 + (size_t)(tm + row) * GK + k0 + chunk * 8;
                dst = sb + row * ROWB + chunk * 16;
            } else {
                int v = u - 512;
                int row = v >> 2, chunk = v & 3;
                src = B16 + (size_t)(tn + row) * GK + k0 + chunk * 8;
                dst = sb + TILEB + row * ROWB + chunk * 16;
            }
            cpa16(dst, src);
        }
        asm volatile("cp.async.commit_group;" ::: "memory");
    };

    issue_load(0, 0);
    issue_load(1, 1);
    issue_load(2, 2);

    int arow_l = (lane & 7) + ((lane >> 3) & 1) * 8;
    int acol   = (lane >> 4) * 8;
    int brow_l = (lane & 7) + ((lane >> 4) & 1) * 8;
    int bcol   = ((lane >> 3) & 1) * 8;

    for (int kc = 0; kc < 64; kc++) {
        if (kc < 62)       asm volatile("cp.async.wait_group 2;" ::: "memory");
        else if (kc == 62) asm volatile("cp.async.wait_group 1;" ::: "memory");
        else               asm volatile("cp.async.wait_group 0;" ::: "memory");
        __syncthreads();
        if (kc + 3 < 64) issue_load(kc + 3, (kc + 3) & 3);

        uint32_t sb = sbase + (kc & 3) * STAGEB;
#pragma unroll
        for (int ks = 0; ks < 2; ks++) {
            uint32_t a_regs[4][4];
#pragma unroll
            for (int i = 0; i < 4; i++)
                ldsm4(a_regs[i],
                      sb + (wm * 64 + i * 16 + arow_l) * ROWB + (ks * 16 + acol) * 2);
            uint32_t b_regs[4][4];
#pragma unroll
            for (int j = 0; j < 4; j++)
                ldsm4(b_regs[j], sb + TILEB +
                      (wn * 64 + j * 16 + brow_l) * ROWB + (ks * 16 + bcol) * 2);
#pragma unroll
            for (int i = 0; i < 4; i++)
#pragma unroll
                for (int j = 0; j < 8; j++)
                    mma16816(acc[i][j], a_regs[i],
                             b_regs[j >> 1][(j & 1) * 2],
                             b_regs[j >> 1][(j & 1) * 2 + 1]);
        }
    }

    int g = lane >> 2, tg = lane & 3;
#pragma unroll
    for (int i = 0; i < 4; i++) {
        int row0 = tm + wm * 64 + i * 16 + g;
#pragma unroll
        for (int j = 0; j < 8; j++) {
            int col = tn + wn * 64 + j * 8 + tg * 2;
            float v0 = acc[i][j][0], v1 = acc[i][j][1];
            float v2 = acc[i][j][2], v3 = acc[i][j][3];
            if (mode) {
                float b0 = bias[col], b1 = bias[col + 1];
                v0 += b0; v1 += b1; v2 += b0; v3 += b1;
                if (col < 2560) {
                    v0 = fmaxf(v0, 0.f); v1 = fmaxf(v1, 0.f);
                    v2 = fmaxf(v2, 0.f); v3 = fmaxf(v3, 0.f);
                    if (col < 2048) {
                        const float s = 0.08838834764831843f;
                        v0 *= s; v1 *= s; v2 *= s; v3 *= s;
                    }
                }
                __half2 h0 = __floats2half2_rn(v0, v1);
                __half2 h1 = __floats2half2_rn(v2, v3);
                if (col < 2048) {
                    *(__half2*)(g_q16 + (size_t)row0 * 2048 + col) = h0;
                    *(__half2*)(g_q16 + (size_t)(row0 + 8) * 2048 + col) = h1;
                } else if (col < 2560) {
                    *(__half2*)(g_k16 + (size_t)row0 * 512 + col - 2048) = h0;
                    *(__half2*)(g_k16 + (size_t)(row0 + 8) * 512 + col - 2048) = h1;
                } else {
                    *(__half2*)(g_v16 + (size_t)row0 * 512 + col - 2560) = h0;
                    *(__half2*)(g_v16 + (size_t)(row0 + 8) * 512 + col - 2560) = h1;
                }
            } else {
                *(float2*)(C + (size_t)row0 * N + col)       = make_float2(v0, v1);
                *(float2*)(C + (size_t)(row0 + 8) * N + col) = make_float2(v2, v3);
            }
        }
    }
}

// ---------------- gateB: gk2 (low-rank proj + logsigmoid) + cumsum + k scale ---
__global__ void __launch_bounds__(128) gateB_kernel(const float* __restrict__ w1,
                                                    const float* __restrict__ b1) {
    __shared__ float stmp[CH][16];
    int c = blockIdx.x, kv = blockIdx.y, d = threadIdx.x;
    int n = kv * 128 + d;
    for (int u = d; u < CH * 16; u += 128) {
        int t = u >> 4, r = u & 15;
        stmp[t][r] = g_tmp16[((size_t)c * CH + t) * 16 + r];
    }
    __syncthreads();
    float w1c[16];
#pragma unroll
    for (int r = 0; r < 16; r++) w1c[r] = w1[r * 512 + n];
    float bb = b1[n];

    float cum = 0.f;
    for (int t = 0; t < CH; t++) {
        float x = bb;
#pragma unroll
        for (int r = 0; r < 16; r++) x += stmp[t][r] * w1c[r];
        float ls = (x >= 0.f) ? (-log1pf(expf(-x))) : (x - log1pf(expf(x)));
        cum += ls * (1.f / 16.f);
        float e = expf(cum);
        size_t gi = ((size_t)c * CH + t) * 512 + n;
        g_eB[gi] = e;
        g_k16[gi] = __float2half_rn(__half2float(g_k16[gi]) * (1.f / e));
    }
    g_EB[(size_t)(c * 4 + kv) * 128 + d] = expf(cum);
}

// ---------------- chunkP via mma: P = exp(Btot) ⊙ (K~^T V), fp16 out ----------
__global__ void __launch_bounds__(256) chunkP_kernel() {
    __shared__ __half sK[64 * 136];
    __shared__ __half sV[64 * 136];
    int c = blockIdx.x, kv = blockIdx.y, tid = threadIdx.x;
    int wid = tid >> 5, lane = tid & 31;
    uint32_t skb = smem_u32(sK), svb = smem_u32(sV);
    const __half* kg = g_k16 + (size_t)c * CH * 512 + kv * 128;
    const __half* vg = g_v16 + (size_t)c * CH * 512 + kv * 128;
    for (int u = tid; u < 2048; u += 256) {
        int r = (u >> 4) & 63, ch = u & 15;
        if (u < 1024)
            cpa16(skb + r * 272 + ch * 16, kg + (size_t)r * 512 + ch * 8);
        else
            cpa16(svb + r * 272 + ch * 16, vg + (size_t)r * 512 + ch * 8);
    }
    asm volatile("cp.async.commit_group;" ::: "memory");
    asm volatile("cp.async.wait_group 0;" ::: "memory");
    __syncthreads();

    int wm = wid & 3, wn = wid >> 2;          // warp tile 32(dk) x 64(dv)
    int atrow = (lane & 7) + ((lane >> 4) & 1) * 8;
    int atcol = ((lane >> 3) & 1) * 8;
    int trow  = lane & 15;
    int tcol  = (lane >> 4) * 8;

    float acc[2][8][4];
#pragma unroll
    for (int i = 0; i < 2; i++)
#pragma unroll
        for (int j = 0; j < 8; j++)
#pragma unroll
            for (int r = 0; r < 4; r++) acc[i][j][r] = 0.f;

#pragma unroll
    for (int kk = 0; kk < 4; kk++) {
        uint32_t ar[2][4];
#pragma unroll
        for (int i = 0; i < 2; i++)
            ldsm4t(ar[i], skb + (kk * 16 + atrow) * 272 +
                           (wm * 32 + i * 16 + atcol) * 2);
        uint32_t bv[4][4];
#pragma unroll
        for (int jb = 0; jb < 4; jb++)
            ldsm4t(bv[jb], svb + (kk * 16 + trow) * 272 +
                            (wn * 64 + jb * 16 + tcol) * 2);
#pragma unroll
        for (int i = 0; i < 2; i++)
#pragma unroll
            for (int j = 0; j < 8; j++)
                mma16816(acc[i][j], ar[i],
                         bv[j >> 1][(j & 1) * 2], bv[j >> 1][(j & 1) * 2 + 1]);
    }

    int rg = lane >> 2, cg = lane & 3;
    const float* ebb = g_EB + (size_t)(c * 4 + kv) * 128;
    __half* pbase = g_P16 + (size_t)(c * 4 + kv) * 16384;
#pragma unroll
    for (int i = 0; i < 2; i++) {
        int dk0 = wm * 32 + i * 16 + rg;
        float eb0 = ebb[dk0], eb1 = ebb[dk0 + 8];
#pragma unroll
        for (int j = 0; j < 8; j++) {
            int dv = wn * 64 + j * 8 + cg * 2;
            *(__half2*)(pbase + (size_t)dk0 * 128 + dv) =
                __floats2half2_rn(acc[i][j][0] * eb0, acc[i][j][1] * eb0);
            *(__half2*)(pbase + (size_t)(dk0 + 8) * 128 + dv) =
                __floats2half2_rn(acc[i][j][2] * eb1, acc[i][j][3] * eb1);
        }
    }
}

// ---------------- inter-chunk combine: element-parallel, fp16 in/out -----------
__global__ void __launch_bounds__(256) combine_kernel() {
    int g = blockIdx.x * 256 + threadIdx.x;
    int dv = g & 127, dk = (g >> 7) & 127, kv = g >> 14;
    float s = 0.f;
    for (int c = 0; c < NC; c++) {
        size_t idx = ((size_t)(c * 4 + kv) * 128 + dk) * 128 + dv;
        g_S16[idx] = __float2half_rn(s);
        float eb = g_EB[(size_t)(c * 4 + kv) * 128 + dk];
        s = eb * s + __half2float(g_P16[idx]);
    }
}

// ---------------- intra-chunk output: grid (NC, NKV), loop 4 heads -------------
#define OQ   0
#define OK   17408
#define OV   34816
#define OS   52224
#define OA   87040
#define ORED 96256
#define OSMEM 96768

__global__ void __launch_bounds__(256) out_kernel(const float* __restrict__ gnw) {
    extern __shared__ char smraw[];
    uint32_t sb = smem_u32(smraw);
    float* sred = (float*)(smraw + ORED);        // [64][2]
    int c = blockIdx.x, kv = blockIdx.y;
    int tid = threadIdx.x, wid = tid >> 5, lane = tid & 31;
    int wm = wid >> 1, wn = wid & 1;

    const __half* kg = g_k16 + (size_t)c * CH * 512 + kv * 128;
    const __half* vg = g_v16 + (size_t)c * CH * 512 + kv * 128;
    const __half* sg = g_S16 + (size_t)(c * 4 + kv) * 16384;
    const float*  ebb = g_eB + (size_t)c * CH * 512 + kv * 128;

    {
        const __half* qg = g_q16 + (size_t)c * CH * 2048 + (kv * 4) * 128;
        for (int u = tid; u < 5120; u += 256) {
            int r, ch;
            if (u < 1024) {
                r = u >> 4; ch = u & 15;
                cpa16(sb + OQ + r * 272 + ch * 16, qg + (size_t)r * 2048 + ch * 8);
            } else if (u < 2048) {
                int v = u - 1024; r = v >> 4; ch = v & 15;
                cpa16(sb + OK + r * 272 + ch * 16, kg + (size_t)r * 512 + ch * 8);
            } else if (u < 3072) {
                int v = u - 2048; r = v >> 4; ch = v & 15;
                cpa16(sb + OV + r * 272 + ch * 16, vg + (size_t)r * 512 + ch * 8);
            } else {
                int v = u - 3072; r = v >> 4; ch = v & 15;
                cpa16(sb + OS + r * 272 + ch * 16, sg + (size_t)r * 128 + ch * 8);
            }
        }
        asm volatile("cp.async.commit_group;" ::: "memory");
        asm volatile("cp.async.wait_group 0;" ::: "memory");
        __syncthreads();
    }

    int arow_l = (lane & 7) + ((lane >> 3) & 1) * 8;
    int acol   = (lane >> 4) * 8;
    int brow_l = (lane & 7) + ((lane >> 4) & 1) * 8;
    int bcol   = ((lane >> 3) & 1) * 8;
    int trow   = lane & 15;
    int tcol   = (lane >> 4) * 8;
    int rg = lane >> 2, cg = lane & 3;

    for (int hl = 0; hl < 4; hl++) {
        int h = kv * 4 + hl;
        if (hl > 0) {
            const __half* qg = g_q16 + (size_t)c * CH * 2048 + h * 128;
            for (int u = tid; u < 1024; u += 256) {
                int r = u >> 4, ch = u & 15;
                cpa16(sb + OQ + r * 272 + ch * 16, qg + (size_t)r * 2048 + ch * 8);
            }
            asm volatile("cp.async.commit_group;" ::: "memory");
            asm volatile("cp.async.wait_group 0;" ::: "memory");
            __syncthreads();
        }

        // scale Q tile in smem by exp(B)
        for (int u = tid; u < 64 * 64; u += 256) {
            int r = u >> 6, c2 = u & 63;
            __half2* qp = (__half2*)(smraw + OQ + r * 272 + c2 * 4);
            float2 e = *(const float2*)(ebb + (size_t)r * 512 + c2 * 2);
            float2 qf = __half22float2(*qp);
            *qp = __floats2half2_rn(qf.x * e.x, qf.y * e.y);
        }
        __syncthreads();

        // phase 1: A = Q K^T (64x64), causal mask -> sA fp16
        {
            float aacc[4][4];
#pragma unroll
            for (int i = 0; i < 4; i++)
#pragma unroll
                for (int j = 0; j < 4; j++) aacc[i][j] = 0.f;
#pragma unroll
            for (int kk = 0; kk < 8; kk++) {
                uint32_t ar[4];
                ldsm4(ar, sb + OQ + (wm * 16 + arow_l) * 272 + (kk * 16 + acol) * 2);
                uint32_t br[2][4];
#pragma unroll
                for (int j = 0; j < 2; j++)
                    ldsm4(br[j], sb + OK + (wn * 32 + j * 16 + brow_l) * 272 +
                                  (kk * 16 + bcol) * 2);
#pragma unroll
                for (int jj = 0; jj < 4; jj++)
                    mma16816(aacc[jj], ar,
                             br[jj >> 1][(jj & 1) * 2], br[jj >> 1][(jj & 1) * 2 + 1]);
            }
            __half* sA = (__half*)(smraw + OA);
#pragma unroll
            for (int jj = 0; jj < 4; jj++) {
                int col = wn * 32 + jj * 8 + cg * 2;
                int r0 = wm * 16 + rg;
                sA[r0 * 72 + col]     = __float2half_rn((col     <= r0) ? aacc[jj][0] : 0.f);
                sA[r0 * 72 + col + 1] = __float2half_rn((col + 1 <= r0) ? aacc[jj][1] : 0.f);
                int r1 = r0 + 8;
                sA[r1 * 72 + col]     = __float2half_rn((col     <= r1) ? aacc[jj][2] : 0.f);
                sA[r1 * 72 + col + 1] = __float2half_rn((col + 1 <= r1) ? aacc[jj][3] : 0.f);
            }
        }
        __syncthreads();

        // phase 2: O = Q S + A V (64x128), warp tile 16x64
        float oacc[8][4];
#pragma unroll
        for (int j = 0; j < 8; j++)
#pragma unroll
            for (int r = 0; r < 4; r++) oacc[j][r] = 0.f;

#pragma unroll
        for (int kk = 0; kk < 8; kk++) {
            uint32_t ar[4];
            ldsm4(ar, sb + OQ + (wm * 16 + arow_l) * 272 + (kk * 16 + acol) * 2);
            uint32_t bt[4][4];
#pragma unroll
            for (int jb = 0; jb < 4; jb++)
                ldsm4t(bt[jb], sb + OS + (kk * 16 + trow) * 272 +
                               (wn * 64 + jb * 16 + tcol) * 2);
#pragma unroll
            for (int j = 0; j < 8; j++)
                mma16816(oacc[j], ar,
                         bt[j >> 1][(j & 1) * 2], bt[j >> 1][(j & 1) * 2 + 1]);
        }
#pragma unroll
        for (int kk = 0; kk < 4; kk++) {
            uint32_t ar[4];
            ldsm4(ar, sb + OA + (wm * 16 + arow_l) * 144 + (kk * 16 + acol) * 2);
            uint32_t bt[4][4];
#pragma unroll
            for (int jb = 0; jb < 4; jb++)
                ldsm4t(bt[jb], sb + OV + (kk * 16 + trow) * 272 +
                               (wn * 64 + jb * 16 + tcol) * 2);
#pragma unroll
            for (int j = 0; j < 8; j++)
                mma16816(oacc[j], ar,
                         bt[j >> 1][(j & 1) * 2], bt[j >> 1][(j & 1) * 2 + 1]);
        }

        // RMSNorm
        float ss0 = 0.f, ss1 = 0.f;
#pragma unroll
        for (int j = 0; j < 8; j++) {
            ss0 += oacc[j][0] * oacc[j][0] + oacc[j][1] * oacc[j][1];
            ss1 += oacc[j][2] * oacc[j][2] + oacc[j][3] * oacc[j][3];
        }
        ss0 += __shfl_xor_sync(0xffffffffu, ss0, 1);
        ss0 += __shfl_xor_sync(0xffffffffu, ss0, 2);
        ss1 += __shfl_xor_sync(0xffffffffu, ss1, 1);
        ss1 += __shfl_xor_sync(0xffffffffu, ss1, 2);
        if (cg == 0) {
            sred[(wm * 16 + rg) * 2 + wn] = ss0;
            sred[(wm * 16 + rg + 8) * 2 + wn] = ss1;
        }
        __syncthreads();
        float tot0 = sred[(wm * 16 + rg) * 2] + sred[(wm * 16 + rg) * 2 + 1];
        float tot1 = sred[(wm * 16 + rg + 8) * 2] + sred[(wm * 16 + rg + 8) * 2 + 1];
        float rn0 = rsqrtf(tot0 * (1.f / 128.f) + 1e-6f);
        float rn1 = rsqrtf(tot1 * (1.f / 128.f) + 1e-6f);

        {
            int r0 = wm * 16 + rg;
            __half* ob0 = g_oA16 + ((size_t)(c * CH) + r0) * 2048 + h * 128;
            __half* ob1 = g_oA16 + ((size_t)(c * CH) + r0 + 8) * 2048 + h * 128;
#pragma unroll
            for (int j = 0; j < 8; j++) {
                int col = wn * 64 + j * 8 + cg * 2;
                float g0 = __ldg(gnw + col), g1 = __ldg(gnw + col + 1);
                *(__half2*)(ob0 + col) =
                    __floats2half2_rn(oacc[j][0] * rn0 * g0, oacc[j][1] * rn0 * g1);
                *(__half2*)(ob1 + col) =
                    __floats2half2_rn(oacc[j][2] * rn1 * g0, oacc[j][3] * rn1 * g1);
            }
        }
        __syncthreads();
    }
}

// ---------------- launch -------------------------------------------------------
extern "C" void kernel_launch(void* const* d_in, const int* in_sizes, int n_in,
                              void* d_out, int out_size) {
    const float* hidden = (const float*)d_in[0];
    const float* Wqkv   = (const float*)d_in[1];
    const float* bqkv   = (const float*)d_in[2];
    const float* gk_w0  = (const float*)d_in[3];
    const float* gk_w1  = (const float*)d_in[4];
    const float* gk_b1  = (const float*)d_in[5];
    const float* gnormw = (const float*)d_in[6];
    const float* Wo     = (const float*)d_in[7];
    float* out = (float*)d_out;

    __half *p_hA16, *p_Wq16, *p_Wo16, *p_oA16;
    cudaGetSymbolAddress((void**)&p_hA16, g_hA16);
    cudaGetSymbolAddress((void**)&p_Wq16, g_Wq16);
    cudaGetSymbolAddress((void**)&p_Wo16, g_Wo16);
    cudaGetSymbolAddress((void**)&p_oA16, g_oA16);

    cudaFuncSetAttribute(gemm_mma, cudaFuncAttributeMaxDynamicSharedMemorySize, GSMEM);
    cudaFuncSetAttribute(out_kernel, cudaFuncAttributeMaxDynamicSharedMemorySize, OSMEM);

    // 0) fused prep: weight transposes + (hidden->fp16 ∪ gk1)
    prep_kernel<<<18432, 256>>>(hidden, Wqkv, Wo, gk_w0, p_hA16, p_Wq16, p_Wo16);

    // 1) qkv projection with fused bias/relu/scale -> fp16 q/k/v
    gemm_mma<<<dim3(QKVW / 128, T_ / 128), 128, GSMEM>>>(
        p_hA16, p_Wq16, bqkv, nullptr, QKVW, 1);

    // 2) gate proj2 + cumsum + k scaling + eB
    gateB_kernel<<<dim3(NC, NKV_), 128>>>(gk_w1, gk_b1);

    // 3) chunked GLA
    chunkP_kernel<<<dim3(NC, NKV_), 256>>>();
    combine_kernel<<<256, 256>>>();
    out_kernel<<<dim3(NC, NKV_), 256, OSMEM>>>(gnormw);

    // 4) o_proj
    gemm_mma<<<dim3(H_ / 128, T_ / 128), 128, GSMEM>>>(
        p_oA16, p_Wo16, nullptr, out, H_, 0);
}

// round 15
// speedup vs baseline: 1.0100x; 1.0100x over previous
#include <cuda_runtime.h>
#include <cuda_fp16.h>
#include <cstdint>
#include <math.h>

#define T_   8192
#define H_   2048
#define NH_  16
#define NKV_ 4
#define D_   128
#define CH   64
#define NC   128          // T_/CH
#define QKVW 3072
#define GK   2048

// ---------------- scratch (static device memory) ------------------------------
__device__ __align__(256) float g_tmp16[(size_t)T_ * 16];
__device__ __align__(256) float g_eB[(size_t)T_ * 512];     // exp(B) per (t,kv,d)
__device__ __align__(256) float g_EB[(size_t)NC * NKV_ * D_];
__device__ __align__(256) __half g_P16[(size_t)NC * NKV_ * D_ * D_];
__device__ __align__(256) __half g_S16[(size_t)NC * NKV_ * D_ * D_];
// fp16 operands
__device__ __align__(256) __half g_hA16[(size_t)T_ * H_];
__device__ __align__(256) __half g_Wq16[(size_t)QKVW * GK];   // [N,K]
__device__ __align__(256) __half g_Wo16[(size_t)H_ * GK];     // [N,K]
__device__ __align__(256) __half g_oA16[(size_t)T_ * H_];
__device__ __align__(256) __half g_q16[(size_t)T_ * 2048];    // q*scale (gate-unscaled)
__device__ __align__(256) __half g_k16[(size_t)T_ * 512];     // k~ after gateB
__device__ __align__(256) __half g_v16[(size_t)T_ * 512];

// ======================= PTX helpers ==========================================
__device__ __forceinline__ uint32_t smem_u32(const void* p) {
    uint32_t a;
    asm("{ .reg .u64 t; cvta.to.shared.u64 t, %1; cvt.u32.u64 %0, t; }" : "=r"(a) : "l"(p));
    return a;
}
__device__ __forceinline__ void cpa16(uint32_t dst, const void* src) {
    asm volatile("cp.async.cg.shared.global [%0], [%1], 16;" :: "r"(dst), "l"(src));
}
__device__ __forceinline__ void ldsm4(uint32_t* r, uint32_t addr) {
    asm volatile("ldmatrix.sync.aligned.m8n8.x4.shared.b16 {%0,%1,%2,%3}, [%4];"
                 : "=r"(r[0]), "=r"(r[1]), "=r"(r[2]), "=r"(r[3]) : "r"(addr));
}
__device__ __forceinline__ void ldsm4t(uint32_t* r, uint32_t addr) {
    asm volatile("ldmatrix.sync.aligned.m8n8.x4.trans.shared.b16 {%0,%1,%2,%3}, [%4];"
                 : "=r"(r[0]), "=r"(r[1]), "=r"(r[2]), "=r"(r[3]) : "r"(addr));
}
__device__ __forceinline__ void mma16816(float* d, const uint32_t* a,
                                         uint32_t b0, uint32_t b1) {
    asm volatile("mma.sync.aligned.m16n8k16.row.col.f32.f16.f16.f32 "
                 "{%0,%1,%2,%3}, {%4,%5,%6,%7}, {%8,%9}, {%0,%1,%2,%3};"
                 : "+f"(d[0]), "+f"(d[1]), "+f"(d[2]), "+f"(d[3])
                 : "r"(a[0]), "r"(a[1]), "r"(a[2]), "r"(a[3]), "r"(b0), "r"(b1));
}

// ======================= fused prep: wtrans x2 + (hidden->fp16 ∪ gk1) ==========
// blocks [0,6144): Wqkv [2048,3072] -> [3072,2048] fp16
// blocks [6144,10240): Wo [2048,2048] -> [2048,2048] fp16
// blocks [10240,18432): row t: hidden fp32 -> fp16 AND gk1 (two-level smem tree)
__global__ void __launch_bounds__(256) prep_kernel(
    const float* __restrict__ hidden, const float* __restrict__ Wqkv,
    const float* __restrict__ Wo, const float* __restrict__ w0,
    __half* __restrict__ hA16, __half* __restrict__ Wq16, __half* __restrict__ Wo16) {
    __shared__ float sred[256][17];
    __shared__ float spart[16][17];
    int b = blockIdx.x, tid = threadIdx.x;
    if (b < 10240) {
        float (*smt)[33] = (float(*)[33])&sred[0][0];
        const float* W;
        __half* out;
        int bx, by, N;
        if (b < 6144) { N = QKVW; bx = b % 96; by = b / 96; W = Wqkv; out = Wq16; }
        else          { int v = b - 6144; N = H_; bx = v % 64; by = v / 64; W = Wo; out = Wo16; }
        int lx = tid & 31, ly = tid >> 5;
        for (int r = ly; r < 32; r += 8)
            smt[r][lx] = W[(size_t)(by * 32 + r) * N + bx * 32 + lx];
        __syncthreads();
        for (int r = ly; r < 32; r += 8)
            out[(size_t)(bx * 32 + r) * GK + by * 32 + lx] = __float2half_rn(smt[lx][r]);
        return;
    }
    // row t: fp16 conversion + gk1 in one pass over hidden[t]
    int t = b - 10240;
    int h0 = tid * 8;
    const float* hrow = hidden + (size_t)t * H_;
    float4 a0 = *(const float4*)(hrow + h0);
    float4 a1 = *(const float4*)(hrow + h0 + 4);
    __half2* dst = (__half2*)(hA16 + (size_t)t * H_ + h0);
    dst[0] = __floats2half2_rn(a0.x, a0.y);
    dst[1] = __floats2half2_rn(a0.z, a0.w);
    dst[2] = __floats2half2_rn(a1.x, a1.y);
    dst[3] = __floats2half2_rn(a1.z, a1.w);

    float acc[16];
#pragma unroll
    for (int r = 0; r < 16; r++) acc[r] = 0.f;
    float xs[8] = {a0.x, a0.y, a0.z, a0.w, a1.x, a1.y, a1.z, a1.w};
#pragma unroll
    for (int j = 0; j < 8; j++) {
        const float4* w = (const float4*)(w0 + (size_t)(h0 + j) * 16);
#pragma unroll
        for (int q = 0; q < 4; q++) {
            float4 w4 = w[q];
            acc[q * 4 + 0] += xs[j] * w4.x;
            acc[q * 4 + 1] += xs[j] * w4.y;
            acc[q * 4 + 2] += xs[j] * w4.z;
            acc[q * 4 + 3] += xs[j] * w4.w;
        }
    }
#pragma unroll
    for (int r = 0; r < 16; r++) sred[tid][r] = acc[r];
    __syncthreads();
    {
        int r = tid & 15, seg = tid >> 4;
        float s = 0.f;
#pragma unroll
        for (int i = 0; i < 16; i++) s += sred[seg * 16 + i][r];
        spart[seg][r] = s;
    }
    __syncthreads();
    if (tid < 16) {
        float s = 0.f;
#pragma unroll
        for (int i = 0; i < 16; i++) s += spart[i][tid];
        g_tmp16[(size_t)t * 16 + tid] = s;
    }
}

// ======================= HMMA GEMM: 128 thr, 4 warps 64x64, 2 CTAs/SM =========
#define ROWB   80
#define TILEB  (128 * ROWB)          // 10240
#define STAGEB (2 * TILEB)           // 20480 (A + B)
#define GSMEM  (4 * STAGEB)          // 81920 -> 2 CTAs/SM

__global__ void __launch_bounds__(128) gemm_mma(
    const __half* __restrict__ A16, const __half* __restrict__ B16,
    const float* __restrict__ bias, float* __restrict__ C, int N, int mode) {
    extern __shared__ char smraw[];
    uint32_t sbase = smem_u32(smraw);
    int tid = threadIdx.x, wid = tid >> 5, lane = tid & 31;
    int tm = blockIdx.y * 128, tn = blockIdx.x * 128;
    int wm = wid & 1, wn = wid >> 1;      // warp tile 64(M) x 64(N)

    float acc[4][8][4];
#pragma unroll
    for (int i = 0; i < 4; i++)
#pragma unroll
        for (int j = 0; j < 8; j++)
#pragma unroll
            for (int r = 0; r < 4; r++) acc[i][j][r] = 0.f;

    auto issue_load = [&](int k0i, int stage) {
        int k0 = k0i * 32;
        uint32_t sb = sbase + stage * STAGEB;
#pragma unroll
        for (int it = 0; it < 8; it++) {
            int u = tid + it * 128;
            const __half* src;
            uint32_t dst;
            if (u < 512) {
                int row = u >> 2, chunk = u & 3;
                src = A16 + (size_t)(tm + row) * GK + k0 + chunk * 8;
                dst = sb + row * ROWB + chunk * 16;
            } else {
                int v = u - 512;
                int row = v >> 2, chunk = v & 3;
                src = B16 + (size_t)(tn + row) * GK + k0 + chunk * 8;
                dst = sb + TILEB + row * ROWB + chunk * 16;
            }
            cpa16(dst, src);
        }
        asm volatile("cp.async.commit_group;" ::: "memory");
    };

    issue_load(0, 0);
    issue_load(1, 1);
    issue_load(2, 2);

    int arow_l = (lane & 7) + ((lane >> 3) & 1) * 8;
    int acol   = (lane >> 4) * 8;
    int brow_l = (lane & 7) + ((lane >> 4) & 1) * 8;
    int bcol   = ((lane >> 3) & 1) * 8;

    for (int kc = 0; kc < 64; kc++) {
        if (kc < 62)       asm volatile("cp.async.wait_group 2;" ::: "memory");
        else if (kc == 62) asm volatile("cp.async.wait_group 1;" ::: "memory");
        else               asm volatile("cp.async.wait_group 0;" ::: "memory");
        __syncthreads();
        if (kc + 3 < 64) issue_load(kc + 3, (kc + 3) & 3);

        uint32_t sb = sbase + (kc & 3) * STAGEB;
#pragma unroll
        for (int ks = 0; ks < 2; ks++) {
            uint32_t a_regs[4][4];
#pragma unroll
            for (int i = 0; i < 4; i++)
                ldsm4(a_regs[i],
                      sb + (wm * 64 + i * 16 + arow_l) * ROWB + (ks * 16 + acol) * 2);
            uint32_t b_regs[4][4];
#pragma unroll
            for (int j = 0; j < 4; j++)
                ldsm4(b_regs[j], sb + TILEB +
                      (wn * 64 + j * 16 + brow_l) * ROWB + (ks * 16 + bcol) * 2);
#pragma unroll
            for (int i = 0; i < 4; i++)
#pragma unroll
                for (int j = 0; j < 8; j++)
                    mma16816(acc[i][j], a_regs[i],
                             b_regs[j >> 1][(j & 1) * 2],
                             b_regs[j >> 1][(j & 1) * 2 + 1]);
        }
    }

    int g = lane >> 2, tg = lane & 3;
#pragma unroll
    for (int i = 0; i < 4; i++) {
        int row0 = tm + wm * 64 + i * 16 + g;
#pragma unroll
        for (int j = 0; j < 8; j++) {
            int col = tn + wn * 64 + j * 8 + tg * 2;
            float v0 = acc[i][j][0], v1 = acc[i][j][1];
            float v2 = acc[i][j][2], v3 = acc[i][j][3];
            if (mode) {
                float b0 = bias[col], b1 = bias[col + 1];
                v0 += b0; v1 += b1; v2 += b0; v3 += b1;
                if (col < 2560) {
                    v0 = fmaxf(v0, 0.f); v1 = fmaxf(v1, 0.f);
                    v2 = fmaxf(v2, 0.f); v3 = fmaxf(v3, 0.f);
                    if (col < 2048) {
                        const float s = 0.08838834764831843f;
                        v0 *= s; v1 *= s; v2 *= s; v3 *= s;
                    }
                }
                __half2 h0 = __floats2half2_rn(v0, v1);
                __half2 h1 = __floats2half2_rn(v2, v3);
                if (col < 2048) {
                    *(__half2*)(g_q16 + (size_t)row0 * 2048 + col) = h0;
                    *(__half2*)(g_q16 + (size_t)(row0 + 8) * 2048 + col) = h1;
                } else if (col < 2560) {
                    *(__half2*)(g_k16 + (size_t)row0 * 512 + col - 2048) = h0;
                    *(__half2*)(g_k16 + (size_t)(row0 + 8) * 512 + col - 2048) = h1;
                } else {
                    *(__half2*)(g_v16 + (size_t)row0 * 512 + col - 2560) = h0;
                    *(__half2*)(g_v16 + (size_t)(row0 + 8) * 512 + col - 2560) = h1;
                }
            } else {
                *(float2*)(C + (size_t)row0 * N + col)       = make_float2(v0, v1);
                *(float2*)(C + (size_t)(row0 + 8) * N + col) = make_float2(v2, v3);
            }
        }
    }
}

// ---------------- gateB: gk2 (low-rank proj + logsigmoid) + cumsum + k scale ---
__global__ void __launch_bounds__(128) gateB_kernel(const float* __restrict__ w1,
                                                    const float* __restrict__ b1) {
    __shared__ float stmp[CH][16];
    int c = blockIdx.x, kv = blockIdx.y, d = threadIdx.x;
    int n = kv * 128 + d;
    for (int u = d; u < CH * 16; u += 128) {
        int t = u >> 4, r = u & 15;
        stmp[t][r] = g_tmp16[((size_t)c * CH + t) * 16 + r];
    }
    __syncthreads();
    float w1c[16];
#pragma unroll
    for (int r = 0; r < 16; r++) w1c[r] = w1[r * 512 + n];
    float bb = b1[n];

    float cum = 0.f;
    for (int t = 0; t < CH; t++) {
        float x = bb;
#pragma unroll
        for (int r = 0; r < 16; r++) x += stmp[t][r] * w1c[r];
        float ls = (x >= 0.f) ? (-log1pf(expf(-x))) : (x - log1pf(expf(x)));
        cum += ls * (1.f / 16.f);
        float e = expf(cum);
        size_t gi = ((size_t)c * CH + t) * 512 + n;
        g_eB[gi] = e;
        g_k16[gi] = __float2half_rn(__half2float(g_k16[gi]) * (1.f / e));
    }
    g_EB[(size_t)(c * 4 + kv) * 128 + d] = expf(cum);
}

// ---------------- chunkP via mma: P = exp(Btot) ⊙ (K~^T V), fp16 out ----------
__global__ void __launch_bounds__(256) chunkP_kernel() {
    __shared__ __half sK[64 * 136];
    __shared__ __half sV[64 * 136];
    int c = blockIdx.x, kv = blockIdx.y, tid = threadIdx.x;
    int wid = tid >> 5, lane = tid & 31;
    uint32_t skb = smem_u32(sK), svb = smem_u32(sV);
    const __half* kg = g_k16 + (size_t)c * CH * 512 + kv * 128;
    const __half* vg = g_v16 + (size_t)c * CH * 512 + kv * 128;
    for (int u = tid; u < 2048; u += 256) {
        int r = (u >> 4) & 63, ch = u & 15;
        if (u < 1024)
            cpa16(skb + r * 272 + ch * 16, kg + (size_t)r * 512 + ch * 8);
        else
            cpa16(svb + r * 272 + ch * 16, vg + (size_t)r * 512 + ch * 8);
    }
    asm volatile("cp.async.commit_group;" ::: "memory");
    asm volatile("cp.async.wait_group 0;" ::: "memory");
    __syncthreads();

    int wm = wid & 3, wn = wid >> 2;          // warp tile 32(dk) x 64(dv)
    int atrow = (lane & 7) + ((lane >> 4) & 1) * 8;
    int atcol = ((lane >> 3) & 1) * 8;
    int trow  = lane & 15;
    int tcol  = (lane >> 4) * 8;

    float acc[2][8][4];
#pragma unroll
    for (int i = 0; i < 2; i++)
#pragma unroll
        for (int j = 0; j < 8; j++)
#pragma unroll
            for (int r = 0; r < 4; r++) acc[i][j][r] = 0.f;

#pragma unroll
    for (int kk = 0; kk < 4; kk++) {
        uint32_t ar[2][4];
#pragma unroll
        for (int i = 0; i < 2; i++)
            ldsm4t(ar[i], skb + (kk * 16 + atrow) * 272 +
                           (wm * 32 + i * 16 + atcol) * 2);
        uint32_t bv[4][4];
#pragma unroll
        for (int jb = 0; jb < 4; jb++)
            ldsm4t(bv[jb], svb + (kk * 16 + trow) * 272 +
                            (wn * 64 + jb * 16 + tcol) * 2);
#pragma unroll
        for (int i = 0; i < 2; i++)
#pragma unroll
            for (int j = 0; j < 8; j++)
                mma16816(acc[i][j], ar[i],
                         bv[j >> 1][(j & 1) * 2], bv[j >> 1][(j & 1) * 2 + 1]);
    }

    int rg = lane >> 2, cg = lane & 3;
    const float* ebb = g_EB + (size_t)(c * 4 + kv) * 128;
    __half* pbase = g_P16 + (size_t)(c * 4 + kv) * 16384;
#pragma unroll
    for (int i = 0; i < 2; i++) {
        int dk0 = wm * 32 + i * 16 + rg;
        float eb0 = ebb[dk0], eb1 = ebb[dk0 + 8];
#pragma unroll
        for (int j = 0; j < 8; j++) {
            int dv = wn * 64 + j * 8 + cg * 2;
            *(__half2*)(pbase + (size_t)dk0 * 128 + dv) =
                __floats2half2_rn(acc[i][j][0] * eb0, acc[i][j][1] * eb0);
            *(__half2*)(pbase + (size_t)(dk0 + 8) * 128 + dv) =
                __floats2half2_rn(acc[i][j][2] * eb1, acc[i][j][3] * eb1);
        }
    }
}

// ---------------- inter-chunk combine: element-parallel, fp16 in/out -----------
__global__ void __launch_bounds__(256) combine_kernel() {
    int g = blockIdx.x * 256 + threadIdx.x;
    int dv = g & 127, dk = (g >> 7) & 127, kv = g >> 14;
    float s = 0.f;
    for (int c = 0; c < NC; c++) {
        size_t idx = ((size_t)(c * 4 + kv) * 128 + dk) * 128 + dv;
        g_S16[idx] = __float2half_rn(s);
        float eb = g_EB[(size_t)(c * 4 + kv) * 128 + dk];
        s = eb * s + __half2float(g_P16[idx]);
    }
}

// ---------------- intra-chunk output: grid (NC, NKV), loop 4 heads -------------
#define OQ   0
#define OK   17408
#define OV   34816
#define OS   52224
#define OA   87040
#define ORED 96256
#define OSMEM 96768

__global__ void __launch_bounds__(256) out_kernel(const float* __restrict__ gnw) {
    extern __shared__ char smraw[];
    uint32_t sb = smem_u32(smraw);
    float* sred = (float*)(smraw + ORED);        // [64][2]
    int c = blockIdx.x, kv = blockIdx.y;
    int tid = threadIdx.x, wid = tid >> 5, lane = tid & 31;
    int wm = wid >> 1, wn = wid & 1;

    const __half* kg = g_k16 + (size_t)c * CH * 512 + kv * 128;
    const __half* vg = g_v16 + (size_t)c * CH * 512 + kv * 128;
    const __half* sg = g_S16 + (size_t)(c * 4 + kv) * 16384;
    const float*  ebb = g_eB + (size_t)c * CH * 512 + kv * 128;

    {
        const __half* qg = g_q16 + (size_t)c * CH * 2048 + (kv * 4) * 128;
        for (int u = tid; u < 5120; u += 256) {
            int r, ch;
            if (u < 1024) {
                r = u >> 4; ch = u & 15;
                cpa16(sb + OQ + r * 272 + ch * 16, qg + (size_t)r * 2048 + ch * 8);
            } else if (u < 2048) {
                int v = u - 1024; r = v >> 4; ch = v & 15;
                cpa16(sb + OK + r * 272 + ch * 16, kg + (size_t)r * 512 + ch * 8);
            } else if (u < 3072) {
                int v = u - 2048; r = v >> 4; ch = v & 15;
                cpa16(sb + OV + r * 272 + ch * 16, vg + (size_t)r * 512 + ch * 8);
            } else {
                int v = u - 3072; r = v >> 4; ch = v & 15;
                cpa16(sb + OS + r * 272 + ch * 16, sg + (size_t)r * 128 + ch * 8);
            }
        }
        asm volatile("cp.async.commit_group;" ::: "memory");
        asm volatile("cp.async.wait_group 0;" ::: "memory");
        __syncthreads();
    }

    int arow_l = (lane & 7) + ((lane >> 3) & 1) * 8;
    int acol   = (lane >> 4) * 8;
    int brow_l = (lane & 7) + ((lane >> 4) & 1) * 8;
    int bcol   = ((lane >> 3) & 1) * 8;
    int trow   = lane & 15;
    int tcol   = (lane >> 4) * 8;
    int rg = lane >> 2, cg = lane & 3;

    for (int hl = 0; hl < 4; hl++) {
        int h = kv * 4 + hl;
        if (hl > 0) {
            const __half* qg = g_q16 + (size_t)c * CH * 2048 + h * 128;
            for (int u = tid; u < 1024; u += 256) {
                int r = u >> 4, ch = u & 15;
                cpa16(sb + OQ + r * 272 + ch * 16, qg + (size_t)r * 2048 + ch * 8);
            }
            asm volatile("cp.async.commit_group;" ::: "memory");
            asm volatile("cp.async.wait_group 0;" ::: "memory");
            __syncthreads();
        }

        // scale Q tile in smem by exp(B)
        for (int u = tid; u < 64 * 64; u += 256) {
            int r = u >> 6, c2 = u & 63;
            __half2* qp = (__half2*)(smraw + OQ + r * 272 + c2 * 4);
            float2 e = *(const float2*)(ebb + (size_t)r * 512 + c2 * 2);
            float2 qf = __half22float2(*qp);
            *qp = __floats2half2_rn(qf.x * e.x, qf.y * e.y);
        }
        __syncthreads();

        // phase 1: A = Q K^T (64x64), causal mask -> sA fp16
        {
            float aacc[4][4];
#pragma unroll
            for (int i = 0; i < 4; i++)
#pragma unroll
                for (int j = 0; j < 4; j++) aacc[i][j] = 0.f;
#pragma unroll
            for (int kk = 0; kk < 8; kk++) {
                uint32_t ar[4];
                ldsm4(ar, sb + OQ + (wm * 16 + arow_l) * 272 + (kk * 16 + acol) * 2);
                uint32_t br[2][4];
#pragma unroll
                for (int j = 0; j < 2; j++)
                    ldsm4(br[j], sb + OK + (wn * 32 + j * 16 + brow_l) * 272 +
                                  (kk * 16 + bcol) * 2);
#pragma unroll
                for (int jj = 0; jj < 4; jj++)
                    mma16816(aacc[jj], ar,
                             br[jj >> 1][(jj & 1) * 2], br[jj >> 1][(jj & 1) * 2 + 1]);
            }
            __half* sA = (__half*)(smraw + OA);
#pragma unroll
            for (int jj = 0; jj < 4; jj++) {
                int col = wn * 32 + jj * 8 + cg * 2;
                int r0 = wm * 16 + rg;
                sA[r0 * 72 + col]     = __float2half_rn((col     <= r0) ? aacc[jj][0] : 0.f);
                sA[r0 * 72 + col + 1] = __float2half_rn((col + 1 <= r0) ? aacc[jj][1] : 0.f);
                int r1 = r0 + 8;
                sA[r1 * 72 + col]     = __float2half_rn((col     <= r1) ? aacc[jj][2] : 0.f);
                sA[r1 * 72 + col + 1] = __float2half_rn((col + 1 <= r1) ? aacc[jj][3] : 0.f);
            }
        }
        __syncthreads();

        // phase 2: O = Q S + A V (64x128), warp tile 16x64
        float oacc[8][4];
#pragma unroll
        for (int j = 0; j < 8; j++)
#pragma unroll
            for (int r = 0; r < 4; r++) oacc[j][r] = 0.f;

#pragma unroll
        for (int kk = 0; kk < 8; kk++) {
            uint32_t ar[4];
            ldsm4(ar, sb + OQ + (wm * 16 + arow_l) * 272 + (kk * 16 + acol) * 2);
            uint32_t bt[4][4];
#pragma unroll
            for (int jb = 0; jb < 4; jb++)
                ldsm4t(bt[jb], sb + OS + (kk * 16 + trow) * 272 +
                               (wn * 64 + jb * 16 + tcol) * 2);
#pragma unroll
            for (int j = 0; j < 8; j++)
                mma16816(oacc[j], ar,
                         bt[j >> 1][(j & 1) * 2], bt[j >> 1][(j & 1) * 2 + 1]);
        }
#pragma unroll
        for (int kk = 0; kk < 4; kk++) {
            uint32_t ar[4];
            ldsm4(ar, sb + OA + (wm * 16 + arow_l) * 144 + (kk * 16 + acol) * 2);
            uint32_t bt[4][4];
#pragma unroll
            for (int jb = 0; jb < 4; jb++)
                ldsm4t(bt[jb], sb + OV + (kk * 16 + trow) * 272 +
                               (wn * 64 + jb * 16 + tcol) * 2);
#pragma unroll
            for (int j = 0; j < 8; j++)
                mma16816(oacc[j], ar,
                         bt[j >> 1][(j & 1) * 2], bt[j >> 1][(j & 1) * 2 + 1]);
        }

        // RMSNorm
        float ss0 = 0.f, ss1 = 0.f;
#pragma unroll
        for (int j = 0; j < 8; j++) {
            ss0 += oacc[j][0] * oacc[j][0] + oacc[j][1] * oacc[j][1];
            ss1 += oacc[j][2] * oacc[j][2] + oacc[j][3] * oacc[j][3];
        }
        ss0 += __shfl_xor_sync(0xffffffffu, ss0, 1);
        ss0 += __shfl_xor_sync(0xffffffffu, ss0, 2);
        ss1 += __shfl_xor_sync(0xffffffffu, ss1, 1);
        ss1 += __shfl_xor_sync(0xffffffffu, ss1, 2);
        if (cg == 0) {
            sred[(wm * 16 + rg) * 2 + wn] = ss0;
            sred[(wm * 16 + rg + 8) * 2 + wn] = ss1;
        }
        __syncthreads();
        float tot0 = sred[(wm * 16 + rg) * 2] + sred[(wm * 16 + rg) * 2 + 1];
        float tot1 = sred[(wm * 16 + rg + 8) * 2] + sred[(wm * 16 + rg + 8) * 2 + 1];
        float rn0 = rsqrtf(tot0 * (1.f / 128.f) + 1e-6f);
        float rn1 = rsqrtf(tot1 * (1.f / 128.f) + 1e-6f);

        {
            int r0 = wm * 16 + rg;
            __half* ob0 = g_oA16 + ((size_t)(c * CH) + r0) * 2048 + h * 128;
            __half* ob1 = g_oA16 + ((size_t)(c * CH) + r0 + 8) * 2048 + h * 128;
#pragma unroll
            for (int j = 0; j < 8; j++) {
                int col = wn * 64 + j * 8 + cg * 2;
                float g0 = __ldg(gnw + col), g1 = __ldg(gnw + col + 1);
                *(__half2*)(ob0 + col) =
                    __floats2half2_rn(oacc[j][0] * rn0 * g0, oacc[j][1] * rn0 * g1);
                *(__half2*)(ob1 + col) =
                    __floats2half2_rn(oacc[j][2] * rn1 * g0, oacc[j][3] * rn1 * g1);
            }
        }
        __syncthreads();
    }
}

// ---------------- launch -------------------------------------------------------
extern "C" void kernel_launch(void* const* d_in, const int* in_sizes, int n_in,
                              void* d_out, int out_size) {
    const float* hidden = (const float*)d_in[0];
    const float* Wqkv   = (const float*)d_in[1];
    const float* bqkv   = (const float*)d_in[2];
    const float* gk_w0  = (const float*)d_in[3];
    const float* gk_w1  = (const float*)d_in[4];
    const float* gk_b1  = (const float*)d_in[5];
    const float* gnormw = (const float*)d_in[6];
    const float* Wo     = (const float*)d_in[7];
    float* out = (float*)d_out;

    __half *p_hA16, *p_Wq16, *p_Wo16, *p_oA16;
    cudaGetSymbolAddress((void**)&p_hA16, g_hA16);
    cudaGetSymbolAddress((void**)&p_Wq16, g_Wq16);
    cudaGetSymbolAddress((void**)&p_Wo16, g_Wo16);
    cudaGetSymbolAddress((void**)&p_oA16, g_oA16);

    cudaFuncSetAttribute(gemm_mma, cudaFuncAttributeMaxDynamicSharedMemorySize, GSMEM);
    cudaFuncSetAttribute(out_kernel, cudaFuncAttributeMaxDynamicSharedMemorySize, OSMEM);

    // 0) fused prep: weight transposes + (hidden->fp16 ∪ gk1, smem tree)
    prep_kernel<<<18432, 256>>>(hidden, Wqkv, Wo, gk_w0, p_hA16, p_Wq16, p_Wo16);

    // 1) qkv projection with fused bias/relu/scale -> fp16 q/k/v
    gemm_mma<<<dim3(QKVW / 128, T_ / 128), 128, GSMEM>>>(
        p_hA16, p_Wq16, bqkv, nullptr, QKVW, 1);

    // 2) gate proj2 + cumsum + k scaling + eB
    gateB_kernel<<<dim3(NC, NKV_), 128>>>(gk_w1, gk_b1);

    // 3) chunked GLA
    chunkP_kernel<<<dim3(NC, NKV_), 256>>>();
    combine_kernel<<<256, 256>>>();
    out_kernel<<<dim3(NC, NKV_), 256, OSMEM>>>(gnormw);

    // 4) o_proj
    gemm_mma<<<dim3(H_ / 128, T_ / 128), 128, GSMEM>>>(
        p_oA16, p_Wo16, nullptr, out, H_, 0);
}

// round 17
// speedup vs baseline: 1.1950x; 1.1831x over previous
#include <cuda_runtime.h>
#include <cuda_fp16.h>
#include <cstdint>
#include <math.h>

#define T_   8192
#define H_   2048
#define NH_  16
#define NKV_ 4
#define D_   128
#define CH   64
#define NC   128          // T_/CH
#define QKVW 3072
#define GK   2048

// ---------------- scratch (static device memory) ------------------------------
__device__ __align__(256) float g_tmp16[(size_t)T_ * 16];
__device__ __align__(256) float g_eB[(size_t)T_ * 512];     // exp(B) per (t,kv,d)
__device__ __align__(256) float g_EB[(size_t)NC * NKV_ * D_];
__device__ __align__(256) __half g_P16[(size_t)NC * NKV_ * D_ * D_];
__device__ __align__(256) __half g_S16[(size_t)NC * NKV_ * D_ * D_];
// fp16 operands
__device__ __align__(256) __half g_hA16[(size_t)T_ * H_];
__device__ __align__(256) __half g_Wq16[(size_t)QKVW * GK];   // [N,K]
__device__ __align__(256) __half g_Wo16[(size_t)H_ * GK];     // [N,K]
__device__ __align__(256) __half g_oA16[(size_t)T_ * H_];
__device__ __align__(256) __half g_q16[(size_t)T_ * 2048];    // q*scale (gate-unscaled)
__device__ __align__(256) __half g_k16[(size_t)T_ * 512];     // k~ after gateB
__device__ __align__(256) __half g_v16[(size_t)T_ * 512];

// ======================= PTX helpers ==========================================
__device__ __forceinline__ uint32_t smem_u32(const void* p) {
    uint32_t a;
    asm("{ .reg .u64 t; cvta.to.shared.u64 t, %1; cvt.u32.u64 %0, t; }" : "=r"(a) : "l"(p));
    return a;
}
__device__ __forceinline__ void cpa16(uint32_t dst, const void* src) {
    asm volatile("cp.async.cg.shared.global [%0], [%1], 16;" :: "r"(dst), "l"(src));
}
__device__ __forceinline__ void ldsm4(uint32_t* r, uint32_t addr) {
    asm volatile("ldmatrix.sync.aligned.m8n8.x4.shared.b16 {%0,%1,%2,%3}, [%4];"
                 : "=r"(r[0]), "=r"(r[1]), "=r"(r[2]), "=r"(r[3]) : "r"(addr));
}
__device__ __forceinline__ void ldsm4t(uint32_t* r, uint32_t addr) {
    asm volatile("ldmatrix.sync.aligned.m8n8.x4.trans.shared.b16 {%0,%1,%2,%3}, [%4];"
                 : "=r"(r[0]), "=r"(r[1]), "=r"(r[2]), "=r"(r[3]) : "r"(addr));
}
__device__ __forceinline__ void mma16816(float* d, const uint32_t* a,
                                         uint32_t b0, uint32_t b1) {
    asm volatile("mma.sync.aligned.m16n8k16.row.col.f32.f16.f16.f32 "
                 "{%0,%1,%2,%3}, {%4,%5,%6,%7}, {%8,%9}, {%0,%1,%2,%3};"
                 : "+f"(d[0]), "+f"(d[1]), "+f"(d[2]), "+f"(d[3])
                 : "r"(a[0]), "r"(a[1]), "r"(a[2]), "r"(a[3]), "r"(b0), "r"(b1));
}

// ======================= fused prep: split + 2x wtrans + gk1 (R13 form) ========
// blocks [0,16384): hidden fp32 -> fp16
// blocks [16384,22528): Wqkv [2048,3072] -> [3072,2048] fp16
// blocks [22528,26624): Wo   [2048,2048] -> [2048,2048] fp16
// blocks [26624,34816): gk1: tmp16 = hidden @ gk_w0
__global__ void __launch_bounds__(256) prep_kernel(
    const float* __restrict__ hidden, const float* __restrict__ Wqkv,
    const float* __restrict__ Wo, const float* __restrict__ w0,
    __half* __restrict__ hA16, __half* __restrict__ Wq16, __half* __restrict__ Wo16) {
    __shared__ float sm[256 * 17];
    int b = blockIdx.x, tid = threadIdx.x;
    if (b < 16384) {
        size_t i4 = ((size_t)b * 256 + tid) * 4;
        float4 v = *(const float4*)(hidden + i4);
        __half2* d = (__half2*)(hA16 + i4);
        d[0] = __floats2half2_rn(v.x, v.y);
        d[1] = __floats2half2_rn(v.z, v.w);
        return;
    }
    if (b < 26624) {
        const float* W;
        __half* out;
        int bx, by, N;
        if (b < 22528) { int v = b - 16384; N = QKVW; bx = v % 96; by = v / 96; W = Wqkv; out = Wq16; }
        else           { int v = b - 22528; N = H_;   bx = v % 64; by = v / 64; W = Wo;   out = Wo16; }
        float (*t)[33] = (float(*)[33])sm;
        int lx = tid & 31, ly = tid >> 5;
        for (int r = ly; r < 32; r += 8)
            t[r][lx] = W[(size_t)(by * 32 + r) * N + bx * 32 + lx];
        __syncthreads();
        for (int r = ly; r < 32; r += 8)
            out[(size_t)(bx * 32 + r) * GK + by * 32 + lx] = __float2half_rn(t[lx][r]);
        return;
    }
    // gk1
    int t = b - 26624;
    float acc[16];
#pragma unroll
    for (int r = 0; r < 16; r++) acc[r] = 0.f;
    const float* hrow = hidden + (size_t)t * H_;
    for (int h = tid; h < H_; h += 256) {
        float x = hrow[h];
        const float4* w = (const float4*)(w0 + (size_t)h * 16);
#pragma unroll
        for (int q = 0; q < 4; q++) {
            float4 w4 = w[q];
            acc[q * 4 + 0] += x * w4.x;
            acc[q * 4 + 1] += x * w4.y;
            acc[q * 4 + 2] += x * w4.z;
            acc[q * 4 + 3] += x * w4.w;
        }
    }
    float (*sred)[17] = (float(*)[17])sm;
#pragma unroll
    for (int r = 0; r < 16; r++) sred[tid][r] = acc[r];
    __syncthreads();
    if (tid < 16) {
        float s = 0.f;
        for (int i = 0; i < 256; i++) s += sred[i][tid];
        g_tmp16[(size_t)t * 16 + tid] = s;
    }
}

// ======================= HMMA GEMM: 128 thr, 4 warps 64x64, 3 stages ==========
// 3 x 20480 = 61440 B smem -> 3 CTAs/SM (12 warps/SM)
#define ROWB   80
#define TILEB  (128 * ROWB)          // 10240
#define STAGEB (2 * TILEB)           // 20480 (A + B)
#define GSMEM  (3 * STAGEB)          // 61440 -> 3 CTAs/SM

__global__ void __launch_bounds__(128) gemm_mma(
    const __half* __restrict__ A16, const __half* __restrict__ B16,
    const float* __restrict__ bias, float* __restrict__ C, int N, int mode) {
    extern __shared__ char smraw[];
    uint32_t sbase = smem_u32(smraw);
    int tid = threadIdx.x, wid = tid >> 5, lane = tid & 31;
    int tm = blockIdx.y * 128, tn = blockIdx.x * 128;
    int wm = wid & 1, wn = wid >> 1;      // warp tile 64(M) x 64(N)

    float acc[4][8][4];
#pragma unroll
    for (int i = 0; i < 4; i++)
#pragma unroll
        for (int j = 0; j < 8; j++)
#pragma unroll
            for (int r = 0; r < 4; r++) acc[i][j][r] = 0.f;

    auto issue_load = [&](int k0i, int stage) {
        int k0 = k0i * 32;
        uint32_t sb = sbase + stage * STAGEB;
#pragma unroll
        for (int it = 0; it < 8; it++) {
            int u = tid + it * 128;
            const __half* src;
            uint32_t dst;
            if (u < 512) {
                int row = u >> 2, chunk = u & 3;
                src = A16 + (size_t)(tm + row) * GK + k0 + chunk * 8;
                dst = sb + row * ROWB + chunk * 16;
            } else {
                int v = u - 512;
                int row = v >> 2, chunk = v & 3;
                src = B16 + (size_t)(tn + row) * GK + k0 + chunk * 8;
                dst = sb + TILEB + row * ROWB + chunk * 16;
            }
            cpa16(dst, src);
        }
        asm volatile("cp.async.commit_group;" ::: "memory");
    };

    issue_load(0, 0);
    issue_load(1, 1);

    int arow_l = (lane & 7) + ((lane >> 3) & 1) * 8;
    int acol   = (lane >> 4) * 8;
    int brow_l = (lane & 7) + ((lane >> 4) & 1) * 8;
    int bcol   = ((lane >> 3) & 1) * 8;

    int st = 0, wst = 2;
    for (int kc = 0; kc < 64; kc++) {
        if (kc < 63) asm volatile("cp.async.wait_group 1;" ::: "memory");
        else         asm volatile("cp.async.wait_group 0;" ::: "memory");
        __syncthreads();
        if (kc + 2 < 64) {
            issue_load(kc + 2, wst);
            if (++wst == 3) wst = 0;
        }

        uint32_t sb = sbase + st * STAGEB;
        if (++st == 3) st = 0;
#pragma unroll
        for (int ks = 0; ks < 2; ks++) {
            uint32_t a_regs[4][4];
#pragma unroll
            for (int i = 0; i < 4; i++)
                ldsm4(a_regs[i],
                      sb + (wm * 64 + i * 16 + arow_l) * ROWB + (ks * 16 + acol) * 2);
            uint32_t b_regs[4][4];
#pragma unroll
            for (int j = 0; j < 4; j++)
                ldsm4(b_regs[j], sb + TILEB +
                      (wn * 64 + j * 16 + brow_l) * ROWB + (ks * 16 + bcol) * 2);
#pragma unroll
            for (int i = 0; i < 4; i++)
#pragma unroll
                for (int j = 0; j < 8; j++)
                    mma16816(acc[i][j], a_regs[i],
                             b_regs[j >> 1][(j & 1) * 2],
                             b_regs[j >> 1][(j & 1) * 2 + 1]);
        }
    }

    int g = lane >> 2, tg = lane & 3;
#pragma unroll
    for (int i = 0; i < 4; i++) {
        int row0 = tm + wm * 64 + i * 16 + g;
#pragma unroll
        for (int j = 0; j < 8; j++) {
            int col = tn + wn * 64 + j * 8 + tg * 2;
            float v0 = acc[i][j][0], v1 = acc[i][j][1];
            float v2 = acc[i][j][2], v3 = acc[i][j][3];
            if (mode) {
                float b0 = bias[col], b1 = bias[col + 1];
                v0 += b0; v1 += b1; v2 += b0; v3 += b1;
                if (col < 2560) {
                    v0 = fmaxf(v0, 0.f); v1 = fmaxf(v1, 0.f);
                    v2 = fmaxf(v2, 0.f); v3 = fmaxf(v3, 0.f);
                    if (col < 2048) {
                        const float s = 0.08838834764831843f;
                        v0 *= s; v1 *= s; v2 *= s; v3 *= s;
                    }
                }
                __half2 h0 = __floats2half2_rn(v0, v1);
                __half2 h1 = __floats2half2_rn(v2, v3);
                if (col < 2048) {
                    *(__half2*)(g_q16 + (size_t)row0 * 2048 + col) = h0;
                    *(__half2*)(g_q16 + (size_t)(row0 + 8) * 2048 + col) = h1;
                } else if (col < 2560) {
                    *(__half2*)(g_k16 + (size_t)row0 * 512 + col - 2048) = h0;
                    *(__half2*)(g_k16 + (size_t)(row0 + 8) * 512 + col - 2048) = h1;
                } else {
                    *(__half2*)(g_v16 + (size_t)row0 * 512 + col - 2560) = h0;
                    *(__half2*)(g_v16 + (size_t)(row0 + 8) * 512 + col - 2560) = h1;
                }
            } else {
                *(float2*)(C + (size_t)row0 * N + col)       = make_float2(v0, v1);
                *(float2*)(C + (size_t)(row0 + 8) * N + col) = make_float2(v2, v3);
            }
        }
    }
}

// ---------------- gateB: gk2 (low-rank proj + logsigmoid) + cumsum + k scale ---
__global__ void __launch_bounds__(128) gateB_kernel(const float* __restrict__ w1,
                                                    const float* __restrict__ b1) {
    __shared__ float stmp[CH][16];
    int c = blockIdx.x, kv = blockIdx.y, d = threadIdx.x;
    int n = kv * 128 + d;
    for (int u = d; u < CH * 16; u += 128) {
        int t = u >> 4, r = u & 15;
        stmp[t][r] = g_tmp16[((size_t)c * CH + t) * 16 + r];
    }
    __syncthreads();
    float w1c[16];
#pragma unroll
    for (int r = 0; r < 16; r++) w1c[r] = w1[r * 512 + n];
    float bb = b1[n];

    float cum = 0.f;
    for (int t = 0; t < CH; t++) {
        float x = bb;
#pragma unroll
        for (int r = 0; r < 16; r++) x += stmp[t][r] * w1c[r];
        float ls = (x >= 0.f) ? (-log1pf(expf(-x))) : (x - log1pf(expf(x)));
        cum += ls * (1.f / 16.f);
        float e = expf(cum);
        size_t gi = ((size_t)c * CH + t) * 512 + n;
        g_eB[gi] = e;
        g_k16[gi] = __float2half_rn(__half2float(g_k16[gi]) * (1.f / e));
    }
    g_EB[(size_t)(c * 4 + kv) * 128 + d] = expf(cum);
}

// ---------------- chunkP via mma: P = exp(Btot) ⊙ (K~^T V), fp16 out ----------
__global__ void __launch_bounds__(256) chunkP_kernel() {
    __shared__ __half sK[64 * 136];
    __shared__ __half sV[64 * 136];
    int c = blockIdx.x, kv = blockIdx.y, tid = threadIdx.x;
    int wid = tid >> 5, lane = tid & 31;
    uint32_t skb = smem_u32(sK), svb = smem_u32(sV);
    const __half* kg = g_k16 + (size_t)c * CH * 512 + kv * 128;
    const __half* vg = g_v16 + (size_t)c * CH * 512 + kv * 128;
    for (int u = tid; u < 2048; u += 256) {
        int r = (u >> 4) & 63, ch = u & 15;
        if (u < 1024)
            cpa16(skb + r * 272 + ch * 16, kg + (size_t)r * 512 + ch * 8);
        else
            cpa16(svb + r * 272 + ch * 16, vg + (size_t)r * 512 + ch * 8);
    }
    asm volatile("cp.async.commit_group;" ::: "memory");
    asm volatile("cp.async.wait_group 0;" ::: "memory");
    __syncthreads();

    int wm = wid & 3, wn = wid >> 2;          // warp tile 32(dk) x 64(dv)
    int atrow = (lane & 7) + ((lane >> 4) & 1) * 8;
    int atcol = ((lane >> 3) & 1) * 8;
    int trow  = lane & 15;
    int tcol  = (lane >> 4) * 8;

    float acc[2][8][4];
#pragma unroll
    for (int i = 0; i < 2; i++)
#pragma unroll
        for (int j = 0; j < 8; j++)
#pragma unroll
            for (int r = 0; r < 4; r++) acc[i][j][r] = 0.f;

#pragma unroll
    for (int kk = 0; kk < 4; kk++) {
        uint32_t ar[2][4];
#pragma unroll
        for (int i = 0; i < 2; i++)
            ldsm4t(ar[i], skb + (kk * 16 + atrow) * 272 +
                           (wm * 32 + i * 16 + atcol) * 2);
        uint32_t bv[4][4];
#pragma unroll
        for (int jb = 0; jb < 4; jb++)
            ldsm4t(bv[jb], svb + (kk * 16 + trow) * 272 +
                            (wn * 64 + jb * 16 + tcol) * 2);
#pragma unroll
        for (int i = 0; i < 2; i++)
#pragma unroll
            for (int j = 0; j < 8; j++)
                mma16816(acc[i][j], ar[i],
                         bv[j >> 1][(j & 1) * 2], bv[j >> 1][(j & 1) * 2 + 1]);
    }

    int rg = lane >> 2, cg = lane & 3;
    const float* ebb = g_EB + (size_t)(c * 4 + kv) * 128;
    __half* pbase = g_P16 + (size_t)(c * 4 + kv) * 16384;
#pragma unroll
    for (int i = 0; i < 2; i++) {
        int dk0 = wm * 32 + i * 16 + rg;
        float eb0 = ebb[dk0], eb1 = ebb[dk0 + 8];
#pragma unroll
        for (int j = 0; j < 8; j++) {
            int dv = wn * 64 + j * 8 + cg * 2;
            *(__half2*)(pbase + (size_t)dk0 * 128 + dv) =
                __floats2half2_rn(acc[i][j][0] * eb0, acc[i][j][1] * eb0);
            *(__half2*)(pbase + (size_t)(dk0 + 8) * 128 + dv) =
                __floats2half2_rn(acc[i][j][2] * eb1, acc[i][j][3] * eb1);
        }
    }
}

// ---------------- inter-chunk combine: element-parallel, fp16 in/out -----------
__global__ void __launch_bounds__(256) combine_kernel() {
    int g = blockIdx.x * 256 + threadIdx.x;
    int dv = g & 127, dk = (g >> 7) & 127, kv = g >> 14;
    float s = 0.f;
    for (int c = 0; c < NC; c++) {
        size_t idx = ((size_t)(c * 4 + kv) * 128 + dk) * 128 + dv;
        g_S16[idx] = __float2half_rn(s);
        float eb = g_EB[(size_t)(c * 4 + kv) * 128 + dk];
        s = eb * s + __half2float(g_P16[idx]);
    }
}

// ---------------- intra-chunk output: grid (NC, NKV), loop 4 heads -------------
#define OQ   0
#define OK   17408
#define OV   34816
#define OS   52224
#define OA   87040
#define ORED 96256
#define OSMEM 96768

__global__ void __launch_bounds__(256) out_kernel(const float* __restrict__ gnw) {
    extern __shared__ char smraw[];
    uint32_t sb = smem_u32(smraw);
    float* sred = (float*)(smraw + ORED);        // [64][2]
    int c = blockIdx.x, kv = blockIdx.y;
    int tid = threadIdx.x, wid = tid >> 5, lane = tid & 31;
    int wm = wid >> 1, wn = wid & 1;

    const __half* kg = g_k16 + (size_t)c * CH * 512 + kv * 128;
    const __half* vg = g_v16 + (size_t)c * CH * 512 + kv * 128;
    const __half* sg = g_S16 + (size_t)(c * 4 + kv) * 16384;
    const float*  ebb = g_eB + (size_t)c * CH * 512 + kv * 128;

    {
        const __half* qg = g_q16 + (size_t)c * CH * 2048 + (kv * 4) * 128;
        for (int u = tid; u < 5120; u += 256) {
            int r, ch;
            if (u < 1024) {
                r = u >> 4; ch = u & 15;
                cpa16(sb + OQ + r * 272 + ch * 16, qg + (size_t)r * 2048 + ch * 8);
            } else if (u < 2048) {
                int v = u - 1024; r = v >> 4; ch = v & 15;
                cpa16(sb + OK + r * 272 + ch * 16, kg + (size_t)r * 512 + ch * 8);
            } else if (u < 3072) {
                int v = u - 2048; r = v >> 4; ch = v & 15;
                cpa16(sb + OV + r * 272 + ch * 16, vg + (size_t)r * 512 + ch * 8);
            } else {
                int v = u - 3072; r = v >> 4; ch = v & 15;
                cpa16(sb + OS + r * 272 + ch * 16, sg + (size_t)r * 128 + ch * 8);
            }
        }
        asm volatile("cp.async.commit_group;" ::: "memory");
        asm volatile("cp.async.wait_group 0;" ::: "memory");
        __syncthreads();
    }

    int arow_l = (lane & 7) + ((lane >> 3) & 1) * 8;
    int acol   = (lane >> 4) * 8;
    int brow_l = (lane & 7) + ((lane >> 4) & 1) * 8;
    int bcol   = ((lane >> 3) & 1) * 8;
    int trow   = lane & 15;
    int tcol   = (lane >> 4) * 8;
    int rg = lane >> 2, cg = lane & 3;

    for (int hl = 0; hl < 4; hl++) {
        int h = kv * 4 + hl;
        if (hl > 0) {
            const __half* qg = g_q16 + (size_t)c * CH * 2048 + h * 128;
            for (int u = tid; u < 1024; u += 256) {
                int r = u >> 4, ch = u & 15;
                cpa16(sb + OQ + r * 272 + ch * 16, qg + (size_t)r * 2048 + ch * 8);
            }
            asm volatile("cp.async.commit_group;" ::: "memory");
            asm volatile("cp.async.wait_group 0;" ::: "memory");
            __syncthreads();
        }

        // scale Q tile in smem by exp(B)
        for (int u = tid; u < 64 * 64; u += 256) {
            int r = u >> 6, c2 = u & 63;
            __half2* qp = (__half2*)(smraw + OQ + r * 272 + c2 * 4);
            float2 e = *(const float2*)(ebb + (size_t)r * 512 + c2 * 2);
            float2 qf = __half22float2(*qp);
            *qp = __floats2half2_rn(qf.x * e.x, qf.y * e.y);
        }
        __syncthreads();

        // phase 1: A = Q K^T (64x64), causal mask -> sA fp16
        {
            float aacc[4][4];
#pragma unroll
            for (int i = 0; i < 4; i++)
#pragma unroll
                for (int j = 0; j < 4; j++) aacc[i][j] = 0.f;
#pragma unroll
            for (int kk = 0; kk < 8; kk++) {
                uint32_t ar[4];
                ldsm4(ar, sb + OQ + (wm * 16 + arow_l) * 272 + (kk * 16 + acol) * 2);
                uint32_t br[2][4];
#pragma unroll
                for (int j = 0; j < 2; j++)
                    ldsm4(br[j], sb + OK + (wn * 32 + j * 16 + brow_l) * 272 +
                                  (kk * 16 + bcol) * 2);
#pragma unroll
                for (int jj = 0; jj < 4; jj++)
                    mma16816(aacc[jj], ar,
                             br[jj >> 1][(jj & 1) * 2], br[jj >> 1][(jj & 1) * 2 + 1]);
            }
            __half* sA = (__half*)(smraw + OA);
#pragma unroll
            for (int jj = 0; jj < 4; jj++) {
                int col = wn * 32 + jj * 8 + cg * 2;
                int r0 = wm * 16 + rg;
                sA[r0 * 72 + col]     = __float2half_rn((col     <= r0) ? aacc[jj][0] : 0.f);
                sA[r0 * 72 + col + 1] = __float2half_rn((col + 1 <= r0) ? aacc[jj][1] : 0.f);
                int r1 = r0 + 8;
                sA[r1 * 72 + col]     = __float2half_rn((col     <= r1) ? aacc[jj][2] : 0.f);
                sA[r1 * 72 + col + 1] = __float2half_rn((col + 1 <= r1) ? aacc[jj][3] : 0.f);
            }
        }
        __syncthreads();

        // phase 2: O = Q S + A V (64x128), warp tile 16x64
        float oacc[8][4];
#pragma unroll
        for (int j = 0; j < 8; j++)
#pragma unroll
            for (int r = 0; r < 4; r++) oacc[j][r] = 0.f;

#pragma unroll
        for (int kk = 0; kk < 8; kk++) {
            uint32_t ar[4];
            ldsm4(ar, sb + OQ + (wm * 16 + arow_l) * 272 + (kk * 16 + acol) * 2);
            uint32_t bt[4][4];
#pragma unroll
            for (int jb = 0; jb < 4; jb++)
                ldsm4t(bt[jb], sb + OS + (kk * 16 + trow) * 272 +
                               (wn * 64 + jb * 16 + tcol) * 2);
#pragma unroll
            for (int j = 0; j < 8; j++)
                mma16816(oacc[j], ar,
                         bt[j >> 1][(j & 1) * 2], bt[j >> 1][(j & 1) * 2 + 1]);
        }
#pragma unroll
        for (int kk = 0; kk < 4; kk++) {
            uint32_t ar[4];
            ldsm4(ar, sb + OA + (wm * 16 + arow_l) * 144 + (kk * 16 + acol) * 2);
            uint32_t bt[4][4];
#pragma unroll
            for (int jb = 0; jb < 4; jb++)
                ldsm4t(bt[jb], sb + OV + (kk * 16 + trow) * 272 +
                               (wn * 64 + jb * 16 + tcol) * 2);
#pragma unroll
            for (int j = 0; j < 8; j++)
                mma16816(oacc[j], ar,
                         bt[j >> 1][(j & 1) * 2], bt[j >> 1][(j & 1) * 2 + 1]);
        }

        // RMSNorm
        float ss0 = 0.f, ss1 = 0.f;
#pragma unroll
        for (int j = 0; j < 8; j++) {
            ss0 += oacc[j][0] * oacc[j][0] + oacc[j][1] * oacc[j][1];
            ss1 += oacc[j][2] * oacc[j][2] + oacc[j][3] * oacc[j][3];
        }
        ss0 += __shfl_xor_sync(0xffffffffu, ss0, 1);
        ss0 += __shfl_xor_sync(0xffffffffu, ss0, 2);
        ss1 += __shfl_xor_sync(0xffffffffu, ss1, 1);
        ss1 += __shfl_xor_sync(0xffffffffu, ss1, 2);
        if (cg == 0) {
            sred[(wm * 16 + rg) * 2 + wn] = ss0;
            sred[(wm * 16 + rg + 8) * 2 + wn] = ss1;
        }
        __syncthreads();
        float tot0 = sred[(wm * 16 + rg) * 2] + sred[(wm * 16 + rg) * 2 + 1];
        float tot1 = sred[(wm * 16 + rg + 8) * 2] + sred[(wm * 16 + rg + 8) * 2 + 1];
        float rn0 = rsqrtf(tot0 * (1.f / 128.f) + 1e-6f);
        float rn1 = rsqrtf(tot1 * (1.f / 128.f) + 1e-6f);

        {
            int r0 = wm * 16 + rg;
            __half* ob0 = g_oA16 + ((size_t)(c * CH) + r0) * 2048 + h * 128;
            __half* ob1 = g_oA16 + ((size_t)(c * CH) + r0 + 8) * 2048 + h * 128;
#pragma unroll
            for (int j = 0; j < 8; j++) {
                int col = wn * 64 + j * 8 + cg * 2;
                float g0 = __ldg(gnw + col), g1 = __ldg(gnw + col + 1);
                *(__half2*)(ob0 + col) =
                    __floats2half2_rn(oacc[j][0] * rn0 * g0, oacc[j][1] * rn0 * g1);
                *(__half2*)(ob1 + col) =
                    __floats2half2_rn(oacc[j][2] * rn1 * g0, oacc[j][3] * rn1 * g1);
            }
        }
        __syncthreads();
    }
}

// ---------------- launch -------------------------------------------------------
extern "C" void kernel_launch(void* const* d_in, const int* in_sizes, int n_in,
                              void* d_out, int out_size) {
    const float* hidden = (const float*)d_in[0];
    const float* Wqkv   = (const float*)d_in[1];
    const float* bqkv   = (const float*)d_in[2];
    const float* gk_w0  = (const float*)d_in[3];
    const float* gk_w1  = (const float*)d_in[4];
    const float* gk_b1  = (const float*)d_in[5];
    const float* gnormw = (const float*)d_in[6];
    const float* Wo     = (const float*)d_in[7];
    float* out = (float*)d_out;

    __half *p_hA16, *p_Wq16, *p_Wo16, *p_oA16;
    cudaGetSymbolAddress((void**)&p_hA16, g_hA16);
    cudaGetSymbolAddress((void**)&p_Wq16, g_Wq16);
    cudaGetSymbolAddress((void**)&p_Wo16, g_Wo16);
    cudaGetSymbolAddress((void**)&p_oA16, g_oA16);

    cudaFuncSetAttribute(gemm_mma, cudaFuncAttributeMaxDynamicSharedMemorySize, GSMEM);
    cudaFuncSetAttribute(out_kernel, cudaFuncAttributeMaxDynamicSharedMemorySize, OSMEM);

    // 0) fused prep: hidden->fp16, both weight transposes, gk1 (R13 form)
    prep_kernel<<<34816, 256>>>(hidden, Wqkv, Wo, gk_w0, p_hA16, p_Wq16, p_Wo16);

    // 1) qkv projection with fused bias/relu/scale -> fp16 q/k/v
    gemm_mma<<<dim3(QKVW / 128, T_ / 128), 128, GSMEM>>>(
        p_hA16, p_Wq16, bqkv, nullptr, QKVW, 1);

    // 2) gate proj2 + cumsum + k scaling + eB
    gateB_kernel<<<dim3(NC, NKV_), 128>>>(gk_w1, gk_b1);

    // 3) chunked GLA
    chunkP_kernel<<<dim3(NC, NKV_), 256>>>();
    combine_kernel<<<256, 256>>>();
    out_kernel<<<dim3(NC, NKV_), 256, OSMEM>>>(gnormw);

    // 4) o_proj
    gemm_mma<<<dim3(H_ / 128, T_ / 128), 128, GSMEM>>>(
        p_oA16, p_Wo16, nullptr, out, H_, 0);
}